// round 1
// baseline (speedup 1.0000x reference)
#include <cuda_runtime.h>
#include <math.h>

#define B_   8
#define T_   4096
#define BT   (B_*T_)          // 32768 rows
#define DM   512
#define NH   8
#define HD   64

// ---------------- scratch (static device globals; no allocation) ------------
__device__ float g_Q   [(size_t)BT * DM];     // Q then rope/elu'd Q   (64 MB)
__device__ float g_C   [(size_t)BT * 128];    // x @ Wd                (16 MB)
__device__ float g_KV  [(size_t)BT * 1024];   // kv raw; K-half roped  (128 MB)
__device__ float g_Attn[(size_t)BT * DM];     // attention output      (64 MB)
__device__ float g_Ctx [B_*NH*HD*HD];         // per-(b,h) 64x64 context
__device__ float g_Ksum[B_*NH*HD];            // per-(b,h) k row-sum

// ---------------- generic tiled SGEMM: C = A[MxK] @ B[KxN] + bias -----------
// BM=BN=128, BK=8, 256 threads, 8x8 per-thread microtile.
__global__ __launch_bounds__(256) void sgemm_bias(
    const float* __restrict__ A, const float* __restrict__ Bm,
    const float* __restrict__ bias, float* __restrict__ C,
    int M, int N, int K)
{
    __shared__ float As[8][128];
    __shared__ float Bs[8][128];
    const int tid = threadIdx.x;
    const int bn  = blockIdx.x;
    const int bm  = blockIdx.y;
    const float* Ab = A  + (size_t)bm * 128 * K;
    const float* Bb = Bm + (size_t)bn * 128;

    const int arow = tid >> 1;          // 0..127
    const int acol = (tid & 1) * 4;     // 0 or 4
    const int brow = tid >> 5;          // 0..7
    const int bcol = (tid & 31) * 4;    // 0..124
    const int tx   = tid & 15;
    const int ty   = tid >> 4;

    float acc[8][8];
    #pragma unroll
    for (int i = 0; i < 8; ++i)
        #pragma unroll
        for (int j = 0; j < 8; ++j) acc[i][j] = 0.f;

    for (int k0 = 0; k0 < K; k0 += 8) {
        float4 av = *(const float4*)(Ab + (size_t)arow * K + k0 + acol);
        As[acol+0][arow] = av.x;
        As[acol+1][arow] = av.y;
        As[acol+2][arow] = av.z;
        As[acol+3][arow] = av.w;
        *(float4*)&Bs[brow][bcol] =
            *(const float4*)(Bb + (size_t)(k0 + brow) * N + bcol);
        __syncthreads();

        #pragma unroll
        for (int k = 0; k < 8; ++k) {
            float ar[8], br[8];
            *(float4*)&ar[0] = *(const float4*)&As[k][ty*8];
            *(float4*)&ar[4] = *(const float4*)&As[k][ty*8+4];
            *(float4*)&br[0] = *(const float4*)&Bs[k][tx*8];
            *(float4*)&br[4] = *(const float4*)&Bs[k][tx*8+4];
            #pragma unroll
            for (int i = 0; i < 8; ++i)
                #pragma unroll
                for (int j = 0; j < 8; ++j)
                    acc[i][j] = fmaf(ar[i], br[j], acc[i][j]);
        }
        __syncthreads();
    }

    const int row0 = bm*128 + ty*8;
    const int col0 = bn*128 + tx*8;
    float bv[8];
    *(float4*)&bv[0] = *(const float4*)(bias + col0);
    *(float4*)&bv[4] = *(const float4*)(bias + col0 + 4);
    #pragma unroll
    for (int i = 0; i < 8; ++i) {
        float4 o0 = make_float4(acc[i][0]+bv[0], acc[i][1]+bv[1],
                                acc[i][2]+bv[2], acc[i][3]+bv[3]);
        float4 o1 = make_float4(acc[i][4]+bv[4], acc[i][5]+bv[5],
                                acc[i][6]+bv[6], acc[i][7]+bv[7]);
        *(float4*)(C + (size_t)(row0+i)*N + col0)     = o0;
        *(float4*)(C + (size_t)(row0+i)*N + col0 + 4) = o1;
    }
}

// ---------------- rope + elu(.)+1 in place on Q and K-half of KV ------------
// One block per row (b*T+t). 256 threads = 8 heads x 32 rotation pairs.
__global__ __launch_bounds__(256) void rope_elu_kernel()
{
    const int row = blockIdx.x;
    const int t   = row & (T_ - 1);
    const int tid = threadIdx.x;
    const int h   = tid >> 5;
    const int j   = tid & 31;

    // freq = 10000^(-j/32) ; theta = t * freq  (match fp32 reference rounding)
    const float LOG2_1E4 = 13.2877123795494f;
    float freq = exp2f(-(float)j * (LOG2_1E4 / 32.f));
    float theta = (float)t * freq;
    float s, c;
    sincosf(theta, &s, &c);

    // Q: head h occupies cols [h*64, h*64+64)
    float* qp = g_Q + (size_t)row * DM + h * HD;
    float x1 = qp[j], x2 = qp[j + 32];
    float r1 = x1 * c - x2 * s;
    float r2 = x1 * s + x2 * c;
    qp[j]      = (r1 > 0.f) ? (r1 + 1.f) : expf(r1);   // elu(x)+1
    qp[j + 32] = (r2 > 0.f) ? (r2 + 1.f) : expf(r2);

    // K: head h occupies cols [h*128, h*128+64) of KV (v is [h*128+64, h*128+128))
    float* kp = g_KV + (size_t)row * 1024 + h * 128;
    x1 = kp[j]; x2 = kp[j + 32];
    r1 = x1 * c - x2 * s;
    r2 = x1 * s + x2 * c;
    kp[j]      = (r1 > 0.f) ? (r1 + 1.f) : expf(r1);
    kp[j + 32] = (r2 > 0.f) ? (r2 + 1.f) : expf(r2);
}

// ---------------- context[b,h] = sum_t k(t) outer v(t); ksum = sum_t k ------
// grid = (T/256 chunks, B*NH pairs). 256 threads, each owns a 4x4 of 64x64.
__global__ __launch_bounds__(256) void context_kernel()
{
    const int p  = blockIdx.y;            // b*8 + h
    const int b  = p >> 3;
    const int h  = p & 7;
    const int t0 = blockIdx.x * 256;

    __shared__ float Ks[32][64];
    __shared__ float Vs[32][64];

    const int tid = threadIdx.x;
    const int tx  = tid & 15;
    const int ty  = tid >> 4;

    float acc[4][4];
    #pragma unroll
    for (int i = 0; i < 4; ++i)
        #pragma unroll
        for (int j = 0; j < 4; ++j) acc[i][j] = 0.f;
    float ksm[4] = {0.f, 0.f, 0.f, 0.f};

    for (int tt = 0; tt < 256; tt += 32) {
        for (int i = tid; i < 512; i += 256) {        // 32 rows x 16 float4
            int r = i >> 4;
            int c = (i & 15) * 4;
            size_t base = (size_t)(b * T_ + t0 + tt + r) * 1024 + h * 128;
            *(float4*)&Ks[r][c] = *(const float4*)(g_KV + base + c);
            *(float4*)&Vs[r][c] = *(const float4*)(g_KV + base + 64 + c);
        }
        __syncthreads();
        #pragma unroll 8
        for (int t = 0; t < 32; ++t) {
            float kr[4], vr[4];
            *(float4*)kr = *(const float4*)&Ks[t][ty*4];
            *(float4*)vr = *(const float4*)&Vs[t][tx*4];
            #pragma unroll
            for (int i = 0; i < 4; ++i)
                #pragma unroll
                for (int j = 0; j < 4; ++j)
                    acc[i][j] = fmaf(kr[i], vr[j], acc[i][j]);
            if (tx == 0) {
                #pragma unroll
                for (int i = 0; i < 4; ++i) ksm[i] += kr[i];
            }
        }
        __syncthreads();
    }

    float* ctx = g_Ctx + (size_t)p * HD * HD;
    #pragma unroll
    for (int i = 0; i < 4; ++i)
        #pragma unroll
        for (int j = 0; j < 4; ++j)
            atomicAdd(&ctx[(ty*4 + i) * HD + tx*4 + j], acc[i][j]);
    if (tx == 0) {
        #pragma unroll
        for (int i = 0; i < 4; ++i)
            atomicAdd(&g_Ksum[p * HD + ty*4 + i], ksm[i]);
    }
}

// ---------------- attn: out = (q @ ctx) * z, z = 1/(q . ksum + 1e-6) --------
// grid = (BT/64 row tiles, NH). Block 256 threads, 4x4 microtile over 64x64.
__global__ __launch_bounds__(256) void attn_kernel()
{
    const int h  = blockIdx.y;
    const int r0 = blockIdx.x * 64;
    const int b  = r0 >> 12;              // r0 / 4096
    const int p  = b * NH + h;

    __shared__ float Cs[64][64];
    __shared__ float Qs[64][65];
    __shared__ float ks[64];
    __shared__ float zs[64];

    const int tid = threadIdx.x;

    for (int i = tid; i < 64*64; i += 256)
        Cs[i >> 6][i & 63] = g_Ctx[(size_t)p * HD * HD + i];
    if (tid < 64) ks[tid] = g_Ksum[p * HD + tid];
    for (int i = tid; i < 64*16; i += 256) {
        int r = i >> 4;
        int c = (i & 15) * 4;
        float4 v = *(const float4*)(g_Q + (size_t)(r0 + r) * DM + h * HD + c);
        Qs[r][c]   = v.x; Qs[r][c+1] = v.y;
        Qs[r][c+2] = v.z; Qs[r][c+3] = v.w;
    }
    __syncthreads();

    if (tid < 64) {
        float dsum = 0.f;
        #pragma unroll
        for (int d = 0; d < 64; ++d) dsum += Qs[tid][d] * ks[d];
        zs[tid] = 1.f / (dsum + 1e-6f);
    }
    __syncthreads();

    const int tx = tid & 15;
    const int ty = tid >> 4;
    float acc[4][4];
    #pragma unroll
    for (int i = 0; i < 4; ++i)
        #pragma unroll
        for (int j = 0; j < 4; ++j) acc[i][j] = 0.f;

    #pragma unroll
    for (int d = 0; d < 64; ++d) {
        float4 cv = *(const float4*)&Cs[d][tx*4];
        float q0 = Qs[ty*4+0][d];
        float q1 = Qs[ty*4+1][d];
        float q2 = Qs[ty*4+2][d];
        float q3 = Qs[ty*4+3][d];
        acc[0][0] = fmaf(q0, cv.x, acc[0][0]); acc[0][1] = fmaf(q0, cv.y, acc[0][1]);
        acc[0][2] = fmaf(q0, cv.z, acc[0][2]); acc[0][3] = fmaf(q0, cv.w, acc[0][3]);
        acc[1][0] = fmaf(q1, cv.x, acc[1][0]); acc[1][1] = fmaf(q1, cv.y, acc[1][1]);
        acc[1][2] = fmaf(q1, cv.z, acc[1][2]); acc[1][3] = fmaf(q1, cv.w, acc[1][3]);
        acc[2][0] = fmaf(q2, cv.x, acc[2][0]); acc[2][1] = fmaf(q2, cv.y, acc[2][1]);
        acc[2][2] = fmaf(q2, cv.z, acc[2][2]); acc[2][3] = fmaf(q2, cv.w, acc[2][3]);
        acc[3][0] = fmaf(q3, cv.x, acc[3][0]); acc[3][1] = fmaf(q3, cv.y, acc[3][1]);
        acc[3][2] = fmaf(q3, cv.z, acc[3][2]); acc[3][3] = fmaf(q3, cv.w, acc[3][3]);
    }

    #pragma unroll
    for (int i = 0; i < 4; ++i) {
        int r = ty*4 + i;
        float z = zs[r];
        float4 o = make_float4(acc[i][0]*z, acc[i][1]*z, acc[i][2]*z, acc[i][3]*z);
        *(float4*)(g_Attn + (size_t)(r0 + r) * DM + h * HD + tx*4) = o;
    }
}

// ---------------------------------------------------------------------------
extern "C" void kernel_launch(void* const* d_in, const int* in_sizes, int n_in,
                              void* d_out, int out_size)
{
    const float* x  = (const float*)d_in[0];
    const float* Wq = (const float*)d_in[1];
    const float* bq = (const float*)d_in[2];
    const float* Wd = (const float*)d_in[3];
    const float* bd = (const float*)d_in[4];
    const float* Wu = (const float*)d_in[5];
    const float* bu = (const float*)d_in[6];
    const float* Wo = (const float*)d_in[7];
    const float* bo = (const float*)d_in[8];
    float* out = (float*)d_out;

    float *pQ, *pC, *pKV, *pAttn, *pCtx, *pKsum;
    cudaGetSymbolAddress((void**)&pQ,    g_Q);
    cudaGetSymbolAddress((void**)&pC,    g_C);
    cudaGetSymbolAddress((void**)&pKV,   g_KV);
    cudaGetSymbolAddress((void**)&pAttn, g_Attn);
    cudaGetSymbolAddress((void**)&pCtx,  g_Ctx);
    cudaGetSymbolAddress((void**)&pKsum, g_Ksum);

    // 1) Q = x @ Wq + bq
    sgemm_bias<<<dim3(DM/128, BT/128), 256>>>(x, Wq, bq, pQ, BT, DM, DM);
    // 2) C = x @ Wd + bd
    sgemm_bias<<<dim3(1, BT/128), 256>>>(x, Wd, bd, pC, BT, 128, DM);
    // 3) KV = C @ Wu + bu
    sgemm_bias<<<dim3(1024/128, BT/128), 256>>>(pC, Wu, bu, pKV, BT, 1024, 128);
    // 4) rope + elu+1 in place (Q fully; K halves of KV)
    rope_elu_kernel<<<BT, 256>>>();
    // 5) zero accumulators, then context reduction
    cudaMemsetAsync(pCtx,  0, sizeof(float) * B_*NH*HD*HD);
    cudaMemsetAsync(pKsum, 0, sizeof(float) * B_*NH*HD);
    context_kernel<<<dim3(T_/256, B_*NH), 256>>>();
    // 6) attention apply + normalization
    attn_kernel<<<dim3(BT/64, NH), 256>>>();
    // 7) out = Attn @ Wo + bo
    sgemm_bias<<<dim3(DM/128, BT/128), 256>>>(pAttn, Wo, bo, out, BT, DM, DM);
}

// round 3
// speedup vs baseline: 1.9237x; 1.9237x over previous
#include <cuda_runtime.h>
#include <cuda_bf16.h>
#include <math.h>
#include <stdint.h>

#define B_   8
#define T_   4096
#define BT   (B_*T_)          // 32768 rows
#define DM   512
#define NH   8
#define HD   64

// ---------------- scratch (static device globals; no allocation) ------------
__device__ float g_Q   [(size_t)BT * DM];      // Q (fp32, roped in place)
__device__ float g_C   [(size_t)BT * 128];     // x @ Wd
__device__ float g_KV  [(size_t)BT * 1024];    // kv; K-half roped in place
__device__ float g_Attn[(size_t)BT * DM];      // attention output
__device__ float g_Ctx [B_*NH*HD*HD];
__device__ float g_Ksum[B_*NH*HD];
// transposed weights [N][K] fp32
__device__ float g_WqT[512*512];
__device__ float g_WdT[128*512];
__device__ float g_WuT[1024*128];
__device__ float g_WoT[512*512];

// ---------------- mma.sync helper (bf16 -> fp32, m16n8k16) ------------------
__device__ __forceinline__ void mma16816(float* d, const uint32_t* a, const uint32_t* b)
{
    asm volatile(
        "mma.sync.aligned.m16n8k16.row.col.f32.bf16.bf16.f32 "
        "{%0,%1,%2,%3}, {%4,%5,%6,%7}, {%8,%9}, {%0,%1,%2,%3};"
        : "+f"(d[0]), "+f"(d[1]), "+f"(d[2]), "+f"(d[3])
        : "r"(a[0]), "r"(a[1]), "r"(a[2]), "r"(a[3]), "r"(b[0]), "r"(b[1]));
}

__device__ __forceinline__ uint32_t pack_bf2(__nv_bfloat16 a, __nv_bfloat16 b)
{
    __nv_bfloat162 p; p.x = a; p.y = b;
    return *(uint32_t*)&p;
}

// ========== HMMA GEMM with 3-term bf16 split: C = A[M,K] @ Bt[N,K]^T + bias =
// 128x128 tile, BK=32, 256 threads (8 warps, 2x4), warp tile 64x32.
#define PADH 40   // smem row stride in halves (conflict-free fragment loads)

__global__ __launch_bounds__(256) void hgemm3(
    const float* __restrict__ A, const float* __restrict__ Bt,
    const float* __restrict__ bias, float* __restrict__ Cout,
    int N, int K)
{
    __shared__ __nv_bfloat16 As_hi[128*PADH];
    __shared__ __nv_bfloat16 As_lo[128*PADH];
    __shared__ __nv_bfloat16 Bs_hi[128*PADH];
    __shared__ __nv_bfloat16 Bs_lo[128*PADH];

    const int tid  = threadIdx.x;
    const int lane = tid & 31;
    const int wid  = tid >> 5;
    const int wm   = (wid >> 2) * 64;       // 0 / 64
    const int wn   = (wid & 3) * 32;        // 0,32,64,96
    const int g    = lane >> 2;             // 0..7
    const int t2   = (lane & 3) * 2;        // 0,2,4,6
    const int m0g  = blockIdx.y * 128;
    const int n0g  = blockIdx.x * 128;

    const float* Ag = A  + (size_t)m0g * K;
    const float* Bg = Bt + (size_t)n0g * K;

    const int jrow = tid >> 3;              // 0..31 (row within tile chunk of 32)
    const int jc4  = (tid & 7) * 4;         // fp32 col within BK=32

    float4 pa[4], pb[4];
    #pragma unroll
    for (int i = 0; i < 4; ++i) {
        int row = jrow + i * 32;
        pa[i] = *(const float4*)(Ag + (size_t)row * K + jc4);
        pb[i] = *(const float4*)(Bg + (size_t)row * K + jc4);
    }

    float acc[4][4][4];
    #pragma unroll
    for (int mt = 0; mt < 4; ++mt)
        #pragma unroll
        for (int nt = 0; nt < 4; ++nt)
            #pragma unroll
            for (int i = 0; i < 4; ++i) acc[mt][nt][i] = 0.f;

    const int nch = K >> 5;
    for (int ch = 0; ch < nch; ++ch) {
        // convert + store prefetched tiles to smem (hi/lo split)
        #pragma unroll
        for (int i = 0; i < 4; ++i) {
            int row = jrow + i * 32;
            int off = row * PADH + jc4;
            float4 v = pa[i];
            __nv_bfloat16 h0 = __float2bfloat16_rn(v.x);
            __nv_bfloat16 h1 = __float2bfloat16_rn(v.y);
            __nv_bfloat16 h2 = __float2bfloat16_rn(v.z);
            __nv_bfloat16 h3 = __float2bfloat16_rn(v.w);
            uint2 hh = make_uint2(pack_bf2(h0,h1), pack_bf2(h2,h3));
            uint2 ll = make_uint2(
                pack_bf2(__float2bfloat16_rn(v.x - __bfloat162float(h0)),
                         __float2bfloat16_rn(v.y - __bfloat162float(h1))),
                pack_bf2(__float2bfloat16_rn(v.z - __bfloat162float(h2)),
                         __float2bfloat16_rn(v.w - __bfloat162float(h3))));
            *(uint2*)&As_hi[off] = hh;
            *(uint2*)&As_lo[off] = ll;
            v = pb[i];
            h0 = __float2bfloat16_rn(v.x);
            h1 = __float2bfloat16_rn(v.y);
            h2 = __float2bfloat16_rn(v.z);
            h3 = __float2bfloat16_rn(v.w);
            hh = make_uint2(pack_bf2(h0,h1), pack_bf2(h2,h3));
            ll = make_uint2(
                pack_bf2(__float2bfloat16_rn(v.x - __bfloat162float(h0)),
                         __float2bfloat16_rn(v.y - __bfloat162float(h1))),
                pack_bf2(__float2bfloat16_rn(v.z - __bfloat162float(h2)),
                         __float2bfloat16_rn(v.w - __bfloat162float(h3))));
            *(uint2*)&Bs_hi[off] = hh;
            *(uint2*)&Bs_lo[off] = ll;
        }
        __syncthreads();

        // prefetch next chunk
        if (ch + 1 < nch) {
            const float* Ag2 = Ag + (ch + 1) * 32;
            const float* Bg2 = Bg + (ch + 1) * 32;
            #pragma unroll
            for (int i = 0; i < 4; ++i) {
                int row = jrow + i * 32;
                pa[i] = *(const float4*)(Ag2 + (size_t)row * K + jc4);
                pb[i] = *(const float4*)(Bg2 + (size_t)row * K + jc4);
            }
        }

        // compute: 2 k16 steps x 3 terms
        #pragma unroll
        for (int ks = 0; ks < 2; ++ks) {
            const int k0 = ks * 16;
            uint32_t ah[4][4], al[4][4];
            #pragma unroll
            for (int mt = 0; mt < 4; ++mt) {
                int base = (wm + mt * 16 + g) * PADH + k0 + t2;
                ah[mt][0] = *(const uint32_t*)&As_hi[base];
                ah[mt][1] = *(const uint32_t*)&As_hi[base + 8 * PADH];
                ah[mt][2] = *(const uint32_t*)&As_hi[base + 8];
                ah[mt][3] = *(const uint32_t*)&As_hi[base + 8 * PADH + 8];
                al[mt][0] = *(const uint32_t*)&As_lo[base];
                al[mt][1] = *(const uint32_t*)&As_lo[base + 8 * PADH];
                al[mt][2] = *(const uint32_t*)&As_lo[base + 8];
                al[mt][3] = *(const uint32_t*)&As_lo[base + 8 * PADH + 8];
            }
            #pragma unroll
            for (int nt = 0; nt < 4; ++nt) {
                int nb = (wn + nt * 8 + g) * PADH + k0 + t2;
                uint32_t bh[2], bl[2];
                bh[0] = *(const uint32_t*)&Bs_hi[nb];
                bh[1] = *(const uint32_t*)&Bs_hi[nb + 8];
                bl[0] = *(const uint32_t*)&Bs_lo[nb];
                bl[1] = *(const uint32_t*)&Bs_lo[nb + 8];
                #pragma unroll
                for (int mt = 0; mt < 4; ++mt) {
                    mma16816(acc[mt][nt], ah[mt], bh);
                    mma16816(acc[mt][nt], al[mt], bh);
                    mma16816(acc[mt][nt], ah[mt], bl);
                }
            }
        }
        __syncthreads();
    }

    // epilogue: add bias, write fp32
    #pragma unroll
    for (int mt = 0; mt < 4; ++mt) {
        int row = m0g + wm + mt * 16 + g;
        #pragma unroll
        for (int nt = 0; nt < 4; ++nt) {
            int col = n0g + wn + nt * 8 + t2;
            float b0 = bias[col], b1 = bias[col + 1];
            float2 o0 = make_float2(acc[mt][nt][0] + b0, acc[mt][nt][1] + b1);
            float2 o1 = make_float2(acc[mt][nt][2] + b0, acc[mt][nt][3] + b1);
            *(float2*)(Cout + (size_t)row * N + col)       = o0;
            *(float2*)(Cout + (size_t)(row + 8) * N + col) = o1;
        }
    }
}

// ---------------- weight transpose: W[K,N] -> Wt[N,K] -----------------------
__global__ __launch_bounds__(256) void transpose_f32(
    const float* __restrict__ W, float* __restrict__ Wt, int K, int N)
{
    __shared__ float t[32][33];
    int kb = blockIdx.y * 32, nb = blockIdx.x * 32;
    int x = threadIdx.x & 31, y = threadIdx.x >> 5;   // 32 x 8
    #pragma unroll
    for (int i = 0; i < 32; i += 8)
        t[y + i][x] = W[(size_t)(kb + y + i) * N + nb + x];
    __syncthreads();
    #pragma unroll
    for (int i = 0; i < 32; i += 8)
        Wt[(size_t)(nb + y + i) * K + kb + x] = t[x][y + i];
}

// ---------------- rope + elu(.)+1 in place on Q and K-half of KV ------------
__global__ __launch_bounds__(256) void rope_elu_kernel()
{
    const int row = blockIdx.x;
    const int t   = row & (T_ - 1);
    const int tid = threadIdx.x;
    const int h   = tid >> 5;
    const int j   = tid & 31;

    const float LOG2_1E4 = 13.2877123795494f;
    float freq = exp2f(-(float)j * (LOG2_1E4 / 32.f));
    float theta = (float)t * freq;
    float s, c;
    sincosf(theta, &s, &c);

    float* qp = g_Q + (size_t)row * DM + h * HD;
    float x1 = qp[j], x2 = qp[j + 32];
    float r1 = x1 * c - x2 * s;
    float r2 = x1 * s + x2 * c;
    qp[j]      = (r1 > 0.f) ? (r1 + 1.f) : expf(r1);
    qp[j + 32] = (r2 > 0.f) ? (r2 + 1.f) : expf(r2);

    float* kp = g_KV + (size_t)row * 1024 + h * 128;
    x1 = kp[j]; x2 = kp[j + 32];
    r1 = x1 * c - x2 * s;
    r2 = x1 * s + x2 * c;
    kp[j]      = (r1 > 0.f) ? (r1 + 1.f) : expf(r1);
    kp[j + 32] = (r2 > 0.f) ? (r2 + 1.f) : expf(r2);
}

// ---------------- context[b,h] = sum_t k(t) outer v(t); ksum = sum_t k ------
__global__ __launch_bounds__(256) void context_kernel()
{
    const int p  = blockIdx.y;
    const int b  = p >> 3;
    const int h  = p & 7;
    const int t0 = blockIdx.x * 256;

    __shared__ float Ks[32][64];
    __shared__ float Vs[32][64];

    const int tid = threadIdx.x;
    const int tx  = tid & 15;
    const int ty  = tid >> 4;

    float acc[4][4];
    #pragma unroll
    for (int i = 0; i < 4; ++i)
        #pragma unroll
        for (int j = 0; j < 4; ++j) acc[i][j] = 0.f;
    float ksm[4] = {0.f, 0.f, 0.f, 0.f};

    for (int tt = 0; tt < 256; tt += 32) {
        for (int i = tid; i < 512; i += 256) {
            int r = i >> 4;
            int c = (i & 15) * 4;
            size_t base = (size_t)(b * T_ + t0 + tt + r) * 1024 + h * 128;
            *(float4*)&Ks[r][c] = *(const float4*)(g_KV + base + c);
            *(float4*)&Vs[r][c] = *(const float4*)(g_KV + base + 64 + c);
        }
        __syncthreads();
        #pragma unroll 8
        for (int t = 0; t < 32; ++t) {
            float kr[4], vr[4];
            *(float4*)kr = *(const float4*)&Ks[t][ty*4];
            *(float4*)vr = *(const float4*)&Vs[t][tx*4];
            #pragma unroll
            for (int i = 0; i < 4; ++i)
                #pragma unroll
                for (int j = 0; j < 4; ++j)
                    acc[i][j] = fmaf(kr[i], vr[j], acc[i][j]);
            if (tx == 0) {
                #pragma unroll
                for (int i = 0; i < 4; ++i) ksm[i] += kr[i];
            }
        }
        __syncthreads();
    }

    float* ctx = g_Ctx + (size_t)p * HD * HD;
    #pragma unroll
    for (int i = 0; i < 4; ++i)
        #pragma unroll
        for (int j = 0; j < 4; ++j)
            atomicAdd(&ctx[(ty*4 + i) * HD + tx*4 + j], acc[i][j]);
    if (tx == 0) {
        #pragma unroll
        for (int i = 0; i < 4; ++i)
            atomicAdd(&g_Ksum[p * HD + ty*4 + i], ksm[i]);
    }
}

// ---------------- attn: out = (q @ ctx) * z, z = 1/(q . ksum + 1e-6) --------
__global__ __launch_bounds__(256) void attn_kernel()
{
    const int h  = blockIdx.y;
    const int r0 = blockIdx.x * 64;
    const int b  = r0 >> 12;
    const int p  = b * NH + h;

    __shared__ float Cs[64][64];
    __shared__ float Qs[64][65];
    __shared__ float ks[64];
    __shared__ float zs[64];

    const int tid = threadIdx.x;

    for (int i = tid; i < 64*64; i += 256)
        Cs[i >> 6][i & 63] = g_Ctx[(size_t)p * HD * HD + i];
    if (tid < 64) ks[tid] = g_Ksum[p * HD + tid];
    for (int i = tid; i < 64*16; i += 256) {
        int r = i >> 4;
        int c = (i & 15) * 4;
        float4 v = *(const float4*)(g_Q + (size_t)(r0 + r) * DM + h * HD + c);
        Qs[r][c]   = v.x; Qs[r][c+1] = v.y;
        Qs[r][c+2] = v.z; Qs[r][c+3] = v.w;
    }
    __syncthreads();

    if (tid < 64) {
        float dsum = 0.f;
        #pragma unroll
        for (int d = 0; d < 64; ++d) dsum += Qs[tid][d] * ks[d];
        zs[tid] = 1.f / (dsum + 1e-6f);
    }
    __syncthreads();

    const int tx = tid & 15;
    const int ty = tid >> 4;
    float acc[4][4];
    #pragma unroll
    for (int i = 0; i < 4; ++i)
        #pragma unroll
        for (int j = 0; j < 4; ++j) acc[i][j] = 0.f;

    #pragma unroll
    for (int d = 0; d < 64; ++d) {
        float4 cv = *(const float4*)&Cs[d][tx*4];
        float q0 = Qs[ty*4+0][d];
        float q1 = Qs[ty*4+1][d];
        float q2 = Qs[ty*4+2][d];
        float q3 = Qs[ty*4+3][d];
        acc[0][0] = fmaf(q0, cv.x, acc[0][0]); acc[0][1] = fmaf(q0, cv.y, acc[0][1]);
        acc[0][2] = fmaf(q0, cv.z, acc[0][2]); acc[0][3] = fmaf(q0, cv.w, acc[0][3]);
        acc[1][0] = fmaf(q1, cv.x, acc[1][0]); acc[1][1] = fmaf(q1, cv.y, acc[1][1]);
        acc[1][2] = fmaf(q1, cv.z, acc[1][2]); acc[1][3] = fmaf(q1, cv.w, acc[1][3]);
        acc[2][0] = fmaf(q2, cv.x, acc[2][0]); acc[2][1] = fmaf(q2, cv.y, acc[2][1]);
        acc[2][2] = fmaf(q2, cv.z, acc[2][2]); acc[2][3] = fmaf(q2, cv.w, acc[2][3]);
        acc[3][0] = fmaf(q3, cv.x, acc[3][0]); acc[3][1] = fmaf(q3, cv.y, acc[3][1]);
        acc[3][2] = fmaf(q3, cv.z, acc[3][2]); acc[3][3] = fmaf(q3, cv.w, acc[3][3]);
    }

    #pragma unroll
    for (int i = 0; i < 4; ++i) {
        int r = ty*4 + i;
        float z = zs[r];
        float4 o = make_float4(acc[i][0]*z, acc[i][1]*z, acc[i][2]*z, acc[i][3]*z);
        *(float4*)(g_Attn + (size_t)(r0 + r) * DM + h * HD + tx*4) = o;
    }
}

// ---------------------------------------------------------------------------
extern "C" void kernel_launch(void* const* d_in, const int* in_sizes, int n_in,
                              void* d_out, int out_size)
{
    const float* x  = (const float*)d_in[0];
    const float* Wq = (const float*)d_in[1];
    const float* bq = (const float*)d_in[2];
    const float* Wd = (const float*)d_in[3];
    const float* bd = (const float*)d_in[4];
    const float* Wu = (const float*)d_in[5];
    const float* bu = (const float*)d_in[6];
    const float* Wo = (const float*)d_in[7];
    const float* bo = (const float*)d_in[8];
    float* out = (float*)d_out;

    float *pQ, *pC, *pKV, *pAttn, *pCtx, *pKsum;
    float *pWqT, *pWdT, *pWuT, *pWoT;
    cudaGetSymbolAddress((void**)&pQ,    g_Q);
    cudaGetSymbolAddress((void**)&pC,    g_C);
    cudaGetSymbolAddress((void**)&pKV,   g_KV);
    cudaGetSymbolAddress((void**)&pAttn, g_Attn);
    cudaGetSymbolAddress((void**)&pCtx,  g_Ctx);
    cudaGetSymbolAddress((void**)&pKsum, g_Ksum);
    cudaGetSymbolAddress((void**)&pWqT,  g_WqT);
    cudaGetSymbolAddress((void**)&pWdT,  g_WdT);
    cudaGetSymbolAddress((void**)&pWuT,  g_WuT);
    cudaGetSymbolAddress((void**)&pWoT,  g_WoT);

    // transpose weights to [N][K]
    transpose_f32<<<dim3(512/32, 512/32), 256>>>(Wq, pWqT, 512, 512);
    transpose_f32<<<dim3(128/32, 512/32), 256>>>(Wd, pWdT, 512, 128);
    transpose_f32<<<dim3(1024/32, 128/32), 256>>>(Wu, pWuT, 128, 1024);
    transpose_f32<<<dim3(512/32, 512/32), 256>>>(Wo, pWoT, 512, 512);

    // Q = x @ Wq + bq
    hgemm3<<<dim3(512/128, BT/128), 256>>>(x, pWqT, bq, pQ, 512, 512);
    // C = x @ Wd + bd
    hgemm3<<<dim3(1, BT/128), 256>>>(x, pWdT, bd, pC, 128, 512);
    // KV = C @ Wu + bu
    hgemm3<<<dim3(1024/128, BT/128), 256>>>(pC, pWuT, bu, pKV, 1024, 128);

    // rope + elu+1 in place
    rope_elu_kernel<<<BT, 256>>>();

    // context reduction
    cudaMemsetAsync(pCtx,  0, sizeof(float) * B_*NH*HD*HD);
    cudaMemsetAsync(pKsum, 0, sizeof(float) * B_*NH*HD);
    context_kernel<<<dim3(T_/256, B_*NH), 256>>>();

    // attention apply + normalization
    attn_kernel<<<dim3(BT/64, NH), 256>>>();

    // out = Attn @ Wo + bo
    hgemm3<<<dim3(512/128, BT/128), 256>>>(pAttn, pWoT, bo, out, 512, 512);
}